// round 8
// baseline (speedup 1.0000x reference)
#include <cuda_runtime.h>
#include <cstdint>

#define BB 32
#define CC 128
#define HH 56
#define WW 56

// ---------------- scratch (module-static device memory; no allocs) ----------------
__device__ uint8_t g_ah[BB * HH * WW * CC];   // u8 high acts, NHWC (128 B/pixel)
__device__ uint8_t g_al[BB * HH * WW * CC];   // u8 low  acts, NHWC (128 B/pixel)
__device__ int8_t  g_wh[CC * 9 * CC];         // s8 high weights [co][k][ci]
__device__ int8_t  g_wlT[9 * 32 * 4 * 4 * 32];// s8 low weights [k][ci4][wn][t][8 words]
__device__ float   g_fsh[CC];                 // fused scale high
__device__ float   g_fsl[CC];                 // fused scale low

__device__ __forceinline__ int dp4a_us(unsigned a, unsigned b, int c) {
    int r;
    asm("dp4a.u32.s32 %0, %1, %2, %3;" : "=r"(r) : "r"(a), "r"(b), "r"(c));
    return r;
}

// ---------------- K1: per-output-channel weight quantization ----------------
__global__ __launch_bounds__(256) void quant_weights_kernel(
    const float* __restrict__ w, const float* __restrict__ as_ptr,
    float nlev, int which)
{
    int co = blockIdx.x;
    int tid = threadIdx.x;
    const float* wc = w + co * (CC * 9);

    float mx = 0.f;
    for (int i = tid; i < CC * 9; i += 256) mx = fmaxf(mx, fabsf(wc[i]));
    __shared__ float red[256];
    red[tid] = mx;
    __syncthreads();
    for (int s = 128; s > 0; s >>= 1) {
        if (tid < s) red[tid] = fmaxf(red[tid], red[tid + s]);
        __syncthreads();
    }
    float s = red[0] / nlev;

    // decomposition for low-weight layout
    int wn = co >> 5, r5 = co & 31;
    int nt = r5 >> 3, tt = (r5 >> 1) & 3, wb = r5 & 1;

    for (int i = tid; i < CC * 9; i += 256) {
        float q = rintf(wc[i] / s);
        q = fminf(fmaxf(q, -nlev), nlev);
        int ci = i / 9, k = i % 9;                 // OIHW: i = ci*9 + k
        if (which == 0) {
            g_wh[(co * 9 + k) * CC + ci] = (int8_t)q;
        } else {
            int ci4 = ci >> 2;
            int word = (((k * 32 + ci4) * 4 + wn) * 4 + tt) * 8 + nt * 2 + wb;
            g_wlT[word * 4 + (ci & 3)] = (int8_t)q;
        }
    }
    if (tid == 0) {
        if (which) g_fsl[co] = s * as_ptr[0];
        else       g_fsh[co] = s * as_ptr[0];
    }
}

// ---------------- K2: predictor mask + activation fake-quant -> NHWC uint8 ----------------
__global__ __launch_bounds__(256) void mask_quant_kernel(
    const float* __restrict__ x,
    const float* __restrict__ ash_p, const float* __restrict__ asl_p)
{
    int bw = blockIdx.x, bh = blockIdx.y, b = blockIdx.z;
    int tid = threadIdx.x;
    int h0 = bh * 8, w0 = bw * 8;

    __shared__ float sx[64][CC + 1];
    __shared__ uint8_t smask[CC];

    for (int i = tid; i < 64 * CC; i += 256) {
        int c = i >> 6, p = i & 63;
        sx[p][c] = x[((b * CC + c) * HH + h0 + (p >> 3)) * WW + w0 + (p & 7)];
    }
    __syncthreads();

    int lane = tid & 31, wrp = tid >> 5;
    for (int j = 0; j < 16; j++) {
        int c = wrp * 16 + j;
        float v = sx[lane][c] + sx[lane + 32][c];
        #pragma unroll
        for (int o = 16; o > 0; o >>= 1) v += __shfl_xor_sync(0xffffffffu, v, o);
        if (lane == 0) smask[c] = (v * (1.0f / 64.0f) >= 0.05f) ? 1 : 0;
    }
    __syncthreads();

    float ash = ash_p[0], asl = asl_p[0];
    for (int i = tid; i < 64 * (CC / 4); i += 256) {
        int p = i >> 5, c4 = (i & 31);
        int hh = h0 + (p >> 3), ww = w0 + (p & 7);
        unsigned qh = 0u, ql = 0u;
        #pragma unroll
        for (int j = 0; j < 4; j++) {
            int c = c4 * 4 + j;
            float v = sx[p][c];
            bool m = smask[c] != 0;
            float fh = fminf(fmaxf(rintf(v / ash), 0.f), 255.f);
            float fl = fminf(fmaxf(rintf(v / asl), 0.f), 15.f);
            unsigned b8h = m ? (unsigned)fh : 0u;
            unsigned b8l = m ? 0u : (unsigned)fl;
            qh |= b8h << (8 * j);
            ql |= b8l << (8 * j);
        }
        int base = ((b * HH + hh) * WW + ww) * (CC / 4) + c4;
        ((unsigned*)g_ah)[base] = qh;
        ((unsigned*)g_al)[base] = ql;
    }
}

// ---------------- K3: hybrid conv3x3 — high via mma (tensor), low via dp4a (fma) ----------------
// CTA: 256 thr = 8 warps (2M x 4N). Tile: 64 pixels (8x8) x 128 co x both convs.
// Warp: 32 pix x 32 co -> B-fragments amortized over 2 M-tiles; dp4a weights
// amortized over 4 pixel-rows with LDS.128 broadcast loads. 2 CTAs/SM.

#define ROWB 144
#define ACT_H_OFF 0
#define ACT_L_OFF 14400                         // 100*144
#define WH_OFF 28800                            // act 2*14400
#define WH_BUF 18432                            // 128*144
#define WL_OFF (28800 + 2 * 18432)              // 65664
#define WL_BUF 16384                            // 32*128*4 (permuted)
#define CONV_SMEM (WL_OFF + 2 * WL_BUF)         // 98432

__device__ __forceinline__ void mma_u8s8(int* c, const unsigned* a, unsigned b0, unsigned b1) {
    asm volatile(
        "mma.sync.aligned.m16n8k32.row.col.s32.u8.s8.s32 "
        "{%0,%1,%2,%3}, {%4,%5,%6,%7}, {%8,%9}, {%0,%1,%2,%3};"
        : "+r"(c[0]), "+r"(c[1]), "+r"(c[2]), "+r"(c[3])
        : "r"(a[0]), "r"(a[1]), "r"(a[2]), "r"(a[3]), "r"(b0), "r"(b1));
}

__device__ __forceinline__ void stage_weights(char* smem, int buf, int k, int tid) {
    unsigned sb = (unsigned)__cvta_generic_to_shared(smem);
    // high: 1024 chunks of 16B (128 co x 8)
    #pragma unroll
    for (int j = 0; j < 4; j++) {
        int i = tid + j * 256;
        int co = i >> 3, c16 = i & 7;
        const char* src = (const char*)g_wh + (co * 9 + k) * CC + c16 * 16;
        unsigned d = sb + WH_OFF + buf * WH_BUF + co * ROWB + c16 * 16;
        asm volatile("cp.async.cg.shared.global [%0], [%1], 16;" :: "r"(d), "l"(src));
    }
    // low (permuted layout, contiguous 16KB per tap): 1024 chunks of 16B
    #pragma unroll
    for (int j = 0; j < 4; j++) {
        int i = tid + j * 256;
        const char* src = (const char*)g_wlT + k * WL_BUF + i * 16;
        unsigned d = sb + WL_OFF + buf * WL_BUF + i * 16;
        asm volatile("cp.async.cg.shared.global [%0], [%1], 16;" :: "r"(d), "l"(src));
    }
}

__global__ __launch_bounds__(256, 2) void conv_hybrid_kernel(float* __restrict__ out)
{
    extern __shared__ __align__(16) char smem[];

    int tid = threadIdx.x;
    int b = blockIdx.z;
    int h0 = blockIdx.y * 8, w0 = blockIdx.x * 8;

    // act halo tiles (both convs): 1600 16B chunks; invalid -> zero store
    #pragma unroll
    for (int j = 0; j < 7; j++) {
        int i = tid + j * 256;
        if (i < 1600) {
            int cv = i / 800, r = i % 800;
            int p = r >> 3, c16 = r & 7;
            int pr = p / 10 - 1 + h0, pc = p % 10 - 1 + w0;
            char* dgen = smem + (cv ? ACT_L_OFF : ACT_H_OFF) + p * ROWB + c16 * 16;
            if (pr >= 0 && pr < HH && pc >= 0 && pc < WW) {
                const char* src = (const char*)(cv ? g_al : g_ah)
                                  + ((size_t)((b * HH + pr) * WW + pc)) * 128 + c16 * 16;
                unsigned d = (unsigned)__cvta_generic_to_shared(dgen);
                asm volatile("cp.async.cg.shared.global [%0], [%1], 16;" :: "r"(d), "l"(src));
            } else {
                *(uint4*)dgen = make_uint4(0u, 0u, 0u, 0u);
            }
        }
    }
    stage_weights(smem, 0, 0, tid);
    asm volatile("cp.async.commit_group;" ::: "memory");

    int lane = tid & 31, warp = tid >> 5;
    int wm = warp >> 2;          // 0..1 : 32-pixel group (pixel rows 4wm..4wm+3)
    int wn = warp & 3;           // 0..3 : 32-co group
    int g = lane >> 2, t = lane & 3;

    int acch[2][4][4], accl[2][4][4];   // [mt][nt][hf*2+w]
    #pragma unroll
    for (int mt = 0; mt < 2; mt++)
        #pragma unroll
        for (int nt = 0; nt < 4; nt++)
            #pragma unroll
            for (int q = 0; q < 4; q++) { acch[mt][nt][q] = 0; accl[mt][nt][q] = 0; }

    const char* s_ah = smem + ACT_H_OFF;
    const char* s_al = smem + ACT_L_OFF;

    #pragma unroll 1
    for (int k9 = 0; k9 < 9; k9++) {
        asm volatile("cp.async.wait_group 0;" ::: "memory");
        __syncthreads();
        int buf = k9 & 1;
        if (k9 < 8) {
            stage_weights(smem, buf ^ 1, k9 + 1, tid);
            asm volatile("cp.async.commit_group;" ::: "memory");
        }
        int kh = k9 / 3, kw = k9 - kh * 3;
        // 4 pixel rows per thread: ph = 4wm + r (r = mt*2 + hf)
        int pin[4];
        #pragma unroll
        for (int r = 0; r < 4; r++)
            pin[r] = (4 * wm + r + kh) * 10 + g + kw;

        // ---- high conv: tensor pipe (m16n8k32 u8s8), 32 MMAs/tap ----
        const char* wcur = smem + WH_OFF + buf * WH_BUF;
        #pragma unroll
        for (int chunk = 0; chunk < 4; chunk++) {
            unsigned a[2][4];
            const char* abase = s_ah + chunk * 32 + t * 4;
            #pragma unroll
            for (int mt = 0; mt < 2; mt++) {
                a[mt][0] = *(const unsigned*)(abase + pin[mt * 2] * ROWB);
                a[mt][1] = *(const unsigned*)(abase + pin[mt * 2 + 1] * ROWB);
                a[mt][2] = *(const unsigned*)(abase + pin[mt * 2] * ROWB + 16);
                a[mt][3] = *(const unsigned*)(abase + pin[mt * 2 + 1] * ROWB + 16);
            }
            #pragma unroll
            for (int nt = 0; nt < 4; nt++) {
                int co = wn * 32 + nt * 8 + g;
                const char* wbp = wcur + co * ROWB + chunk * 32 + t * 4;
                unsigned b0 = *(const unsigned*)wbp;
                unsigned b1 = *(const unsigned*)(wbp + 16);
                mma_u8s8(acch[0][nt], a[0], b0, b1);
                mma_u8s8(acch[1][nt], a[1], b0, b1);
            }
        }

        // ---- low conv: fma pipe (dp4a), weights via broadcast LDS.128 ----
        const char* wlb = smem + WL_OFF + buf * WL_BUF + (wn * 4 + t) * 32;
        #pragma unroll
        for (int seg = 0; seg < 8; seg++) {
            unsigned aw[4][4];
            #pragma unroll
            for (int r = 0; r < 4; r++) {
                uint4 v = *(const uint4*)(s_al + pin[r] * ROWB + seg * 16);
                aw[r][0] = v.x; aw[r][1] = v.y; aw[r][2] = v.z; aw[r][3] = v.w;
            }
            #pragma unroll
            for (int q = 0; q < 4; q++) {
                int ci4 = seg * 4 + q;
                uint4 wv0 = *(const uint4*)(wlb + ci4 * 512);
                uint4 wv1 = *(const uint4*)(wlb + ci4 * 512 + 16);
                #pragma unroll
                for (int r = 0; r < 4; r++) {
                    int mt = r >> 1, e = (r & 1) * 2;
                    accl[mt][0][e]     = dp4a_us(aw[r][q], wv0.x, accl[mt][0][e]);
                    accl[mt][0][e + 1] = dp4a_us(aw[r][q], wv0.y, accl[mt][0][e + 1]);
                    accl[mt][1][e]     = dp4a_us(aw[r][q], wv0.z, accl[mt][1][e]);
                    accl[mt][1][e + 1] = dp4a_us(aw[r][q], wv0.w, accl[mt][1][e + 1]);
                    accl[mt][2][e]     = dp4a_us(aw[r][q], wv1.x, accl[mt][2][e]);
                    accl[mt][2][e + 1] = dp4a_us(aw[r][q], wv1.y, accl[mt][2][e + 1]);
                    accl[mt][3][e]     = dp4a_us(aw[r][q], wv1.z, accl[mt][3][e]);
                    accl[mt][3][e + 1] = dp4a_us(aw[r][q], wv1.w, accl[mt][3][e + 1]);
                }
            }
        }
    }

    // epilogue: y = fsh*acc_h + fsl*acc_l -> NCHW fp32
    int ow = w0 + g;
    #pragma unroll
    for (int nt = 0; nt < 4; nt++) {
        int co0 = wn * 32 + nt * 8 + t * 2;
        float sh0 = g_fsh[co0],     sl0 = g_fsl[co0];
        float sh1 = g_fsh[co0 + 1], sl1 = g_fsl[co0 + 1];
        #pragma unroll
        for (int mt = 0; mt < 2; mt++) {
            #pragma unroll
            for (int hf = 0; hf < 2; hf++) {
                int oh = h0 + 4 * wm + mt * 2 + hf;
                int e = hf * 2;
                out[((b * CC + co0) * HH + oh) * WW + ow] =
                    sh0 * (float)acch[mt][nt][e] + sl0 * (float)accl[mt][nt][e];
                out[((b * CC + co0 + 1) * HH + oh) * WW + ow] =
                    sh1 * (float)acch[mt][nt][e + 1] + sl1 * (float)accl[mt][nt][e + 1];
            }
        }
    }
}

// ---------------- launch ----------------
extern "C" void kernel_launch(void* const* d_in, const int* in_sizes, int n_in,
                              void* d_out, int out_size)
{
    const float* x      = (const float*)d_in[0];
    const float* w_high = (const float*)d_in[1];
    const float* w_low  = (const float*)d_in[2];
    const float* as_h   = (const float*)d_in[3];
    const float* as_l   = (const float*)d_in[4];
    float* out = (float*)d_out;

    cudaFuncSetAttribute(conv_hybrid_kernel,
                         cudaFuncAttributeMaxDynamicSharedMemorySize, CONV_SMEM);

    quant_weights_kernel<<<CC, 256>>>(w_high, as_h, 127.0f, 0);
    quant_weights_kernel<<<CC, 256>>>(w_low,  as_l,   7.0f, 1);
    mask_quant_kernel<<<dim3(WW / 8, HH / 8, BB), 256>>>(x, as_h, as_l);
    conv_hybrid_kernel<<<dim3(WW / 8, HH / 8, BB), 256, CONV_SMEM>>>(out);
}

// round 9
// speedup vs baseline: 1.0268x; 1.0268x over previous
#include <cuda_runtime.h>
#include <cstdint>

#define BB 32
#define CC 128
#define HH 56
#define WW 56

// ---------------- scratch (module-static device memory; no allocs) ----------------
__device__ uint8_t g_ah[BB * HH * WW * CC];   // u8 high acts, NHWC (128 B/pixel)
__device__ uint8_t g_al[BB * HH * WW * CC];   // u8 low  acts, NHWC (128 B/pixel)
__device__ int8_t  g_wh[CC * 9 * CC];         // s8 high weights [co][k][ci] (mma path)
__device__ int8_t  g_whT[9 * 2 * 32 * 64 * 4];// high weights, dp4a broadcast layout
__device__ int8_t  g_wlT[9 * 2 * 32 * 64 * 4];// low  weights, dp4a broadcast layout
// T layout: [k][ch(co>>6)][ci4][wn][t][8 words]; word = nt*2+wb; byte = ci&3
__device__ float   g_fsh[CC];                 // fused scale high
__device__ float   g_fsl[CC];                 // fused scale low

__device__ __forceinline__ int dp4a_us(unsigned a, unsigned b, int c) {
    int r;
    asm("dp4a.u32.s32 %0, %1, %2, %3;" : "=r"(r) : "r"(a), "r"(b), "r"(c));
    return r;
}

// ---------------- K1: per-output-channel weight quantization ----------------
__global__ __launch_bounds__(256) void quant_weights_kernel(
    const float* __restrict__ w, const float* __restrict__ as_ptr,
    float nlev, int which)
{
    int co = blockIdx.x;
    int tid = threadIdx.x;
    const float* wc = w + co * (CC * 9);

    float mx = 0.f;
    for (int i = tid; i < CC * 9; i += 256) mx = fmaxf(mx, fabsf(wc[i]));
    __shared__ float red[256];
    red[tid] = mx;
    __syncthreads();
    for (int s = 128; s > 0; s >>= 1) {
        if (tid < s) red[tid] = fmaxf(red[tid], red[tid + s]);
        __syncthreads();
    }
    float s = red[0] / nlev;

    // decomposition for broadcast dp4a layout
    int ch = co >> 6, r = co & 63;
    int wn = r >> 5, r5 = r & 31;
    int nt = r5 >> 3, tt = (r5 >> 1) & 3, wb = r5 & 1;

    for (int i = tid; i < CC * 9; i += 256) {
        float q = rintf(wc[i] / s);
        q = fminf(fmaxf(q, -nlev), nlev);
        int ci = i / 9, k = i % 9;                 // OIHW: i = ci*9 + k
        int ci4 = ci >> 2;
        int word = (((k * 2 + ch) * 32 + ci4) * 8 + wn * 4 + tt) * 8 + nt * 2 + wb;
        if (which == 0) {
            g_wh[(co * 9 + k) * CC + ci] = (int8_t)q;
            g_whT[word * 4 + (ci & 3)] = (int8_t)q;
        } else {
            g_wlT[word * 4 + (ci & 3)] = (int8_t)q;
        }
    }
    if (tid == 0) {
        if (which) g_fsl[co] = s * as_ptr[0];
        else       g_fsh[co] = s * as_ptr[0];
    }
}

// ---------------- K2: predictor mask + activation fake-quant -> NHWC uint8 ----------------
__global__ __launch_bounds__(256) void mask_quant_kernel(
    const float* __restrict__ x,
    const float* __restrict__ ash_p, const float* __restrict__ asl_p)
{
    int bw = blockIdx.x, bh = blockIdx.y, b = blockIdx.z;
    int tid = threadIdx.x;
    int h0 = bh * 8, w0 = bw * 8;

    __shared__ float sx[64][CC + 1];
    __shared__ uint8_t smask[CC];

    for (int i = tid; i < 64 * CC; i += 256) {
        int c = i >> 6, p = i & 63;
        sx[p][c] = x[((b * CC + c) * HH + h0 + (p >> 3)) * WW + w0 + (p & 7)];
    }
    __syncthreads();

    int lane = tid & 31, wrp = tid >> 5;
    for (int j = 0; j < 16; j++) {
        int c = wrp * 16 + j;
        float v = sx[lane][c] + sx[lane + 32][c];
        #pragma unroll
        for (int o = 16; o > 0; o >>= 1) v += __shfl_xor_sync(0xffffffffu, v, o);
        if (lane == 0) smask[c] = (v * (1.0f / 64.0f) >= 0.05f) ? 1 : 0;
    }
    __syncthreads();

    float ash = ash_p[0], asl = asl_p[0];
    for (int i = tid; i < 64 * (CC / 4); i += 256) {
        int p = i >> 5, c4 = (i & 31);
        int hh = h0 + (p >> 3), ww = w0 + (p & 7);
        unsigned qh = 0u, ql = 0u;
        #pragma unroll
        for (int j = 0; j < 4; j++) {
            int c = c4 * 4 + j;
            float v = sx[p][c];
            bool m = smask[c] != 0;
            float fh = fminf(fmaxf(rintf(v / ash), 0.f), 255.f);
            float fl = fminf(fmaxf(rintf(v / asl), 0.f), 15.f);
            unsigned b8h = m ? (unsigned)fh : 0u;
            unsigned b8l = m ? 0u : (unsigned)fl;
            qh |= b8h << (8 * j);
            ql |= b8l << (8 * j);
        }
        int base = ((b * HH + hh) * WW + ww) * (CC / 4) + c4;
        ((unsigned*)g_ah)[base] = qh;
        ((unsigned*)g_al)[base] = ql;
    }
}

// ---------------- K3: hybrid conv3x3 ----------------
// High conv: ci 0..95 via mma (tensor pipe), ci 96..127 via dp4a -> same acch regs.
// Low conv: all via dp4a. CTA: 256 thr, 8 warps (4M x 2N), warp = 16pix x 32co,
// tile 64 pix x 64 co. 3 CTAs/SM. dp4a weights use broadcast LDS.128 layout.

#define ROWB 144
#define ACT_H_OFF 0
#define ACT_L_OFF 14400                         // 100*144
#define WH_OFF 28800
#define WH_BUF 9216                             // 64co * 144
#define WL_OFF (28800 + 2 * 9216)               // 47232
#define WL_BUF 8192                             // 32 ci4 * 256B
#define WHD_OFF (47232 + 2 * 8192)              // 63616
#define WHD_BUF 2048                            // 8 ci4 * 256B (ci4 24..31)
#define CONV_SMEM (WHD_OFF + 2 * WHD_BUF)       // 67712

__device__ __forceinline__ void mma_u8s8(int* c, const unsigned* a, unsigned b0, unsigned b1) {
    asm volatile(
        "mma.sync.aligned.m16n8k32.row.col.s32.u8.s8.s32 "
        "{%0,%1,%2,%3}, {%4,%5,%6,%7}, {%8,%9}, {%0,%1,%2,%3};"
        : "+r"(c[0]), "+r"(c[1]), "+r"(c[2]), "+r"(c[3])
        : "r"(a[0]), "r"(a[1]), "r"(a[2]), "r"(a[3]), "r"(b0), "r"(b1));
}

__device__ __forceinline__ void stage_weights(char* smem, int buf, int k, int co0, int tid) {
    unsigned sb = (unsigned)__cvta_generic_to_shared(smem);
    int ch = co0 >> 6;
    #pragma unroll
    for (int j = 0; j < 5; j++) {
        int i = tid + j * 256;
        if (i < 512) {
            // high mma weights: 64 co x 8 c16
            int co = i >> 3, c16 = i & 7;
            const char* src = (const char*)g_wh + ((co0 + co) * 9 + k) * CC + c16 * 16;
            unsigned d = sb + WH_OFF + buf * WH_BUF + co * ROWB + c16 * 16;
            asm volatile("cp.async.cg.shared.global [%0], [%1], 16;" :: "r"(d), "l"(src));
        } else if (i < 1024) {
            // low dp4a weights: contiguous 8KB slice
            int r = i - 512;
            const char* src = (const char*)g_wlT + (k * 2 + ch) * 8192 + r * 16;
            unsigned d = sb + WL_OFF + buf * WL_BUF + r * 16;
            asm volatile("cp.async.cg.shared.global [%0], [%1], 16;" :: "r"(d), "l"(src));
        } else if (i < 1152) {
            // high dp4a weights, ci4 24..31: contiguous 2KB slice
            int r = i - 1024;
            const char* src = (const char*)g_whT + (k * 2 + ch) * 8192 + 24 * 256 + r * 16;
            unsigned d = sb + WHD_OFF + buf * WHD_BUF + r * 16;
            asm volatile("cp.async.cg.shared.global [%0], [%1], 16;" :: "r"(d), "l"(src));
        }
    }
}

__global__ __launch_bounds__(256, 3) void conv_hybrid_kernel(float* __restrict__ out)
{
    extern __shared__ __align__(16) char smem[];

    int tid = threadIdx.x;
    int bz = blockIdx.z;
    int b = bz >> 1;
    int co0 = (bz & 1) * 64;
    int h0 = blockIdx.y * 8, w0 = blockIdx.x * 8;

    // act halo tiles (both convs): 1600 16B chunks; invalid -> zero store
    #pragma unroll
    for (int j = 0; j < 7; j++) {
        int i = tid + j * 256;
        if (i < 1600) {
            int cv = i / 800, r = i % 800;
            int p = r >> 3, c16 = r & 7;
            int pr = p / 10 - 1 + h0, pc = p % 10 - 1 + w0;
            char* dgen = smem + (cv ? ACT_L_OFF : ACT_H_OFF) + p * ROWB + c16 * 16;
            if (pr >= 0 && pr < HH && pc >= 0 && pc < WW) {
                const char* src = (const char*)(cv ? g_al : g_ah)
                                  + ((size_t)((b * HH + pr) * WW + pc)) * 128 + c16 * 16;
                unsigned d = (unsigned)__cvta_generic_to_shared(dgen);
                asm volatile("cp.async.cg.shared.global [%0], [%1], 16;" :: "r"(d), "l"(src));
            } else {
                *(uint4*)dgen = make_uint4(0u, 0u, 0u, 0u);
            }
        }
    }
    stage_weights(smem, 0, 0, co0, tid);
    asm volatile("cp.async.commit_group;" ::: "memory");

    int lane = tid & 31, warp = tid >> 5;
    int wm = warp >> 1;          // 0..3 : 16-pixel group
    int wn = warp & 1;           // 0..1 : 32-co group
    int g = lane >> 2, t = lane & 3;

    int acch[4][4], accl[4][4];  // [nt][e]; e: 0,1 = row pin0 co,co+1; 2,3 = row pin1
    #pragma unroll
    for (int nt = 0; nt < 4; nt++)
        #pragma unroll
        for (int q = 0; q < 4; q++) { acch[nt][q] = 0; accl[nt][q] = 0; }

    const char* s_ah = smem + ACT_H_OFF;
    const char* s_al = smem + ACT_L_OFF;

    #pragma unroll 1
    for (int k9 = 0; k9 < 9; k9++) {
        asm volatile("cp.async.wait_group 0;" ::: "memory");
        __syncthreads();
        int buf = k9 & 1;
        if (k9 < 8) {
            stage_weights(smem, buf ^ 1, k9 + 1, co0, tid);
            asm volatile("cp.async.commit_group;" ::: "memory");
        }
        int kh = k9 / 3, kw = k9 - kh * 3;
        int pin0 = (2 * wm + kh) * 10 + g + kw;
        int pin1 = pin0 + 10;

        // ---- high conv, ci 0..95: tensor pipe (3 chunks x 4 nt = 12 MMAs) ----
        const char* wcur = smem + WH_OFF + buf * WH_BUF;
        #pragma unroll
        for (int chunk = 0; chunk < 3; chunk++) {
            unsigned a[4];
            const char* abase = s_ah + chunk * 32 + t * 4;
            a[0] = *(const unsigned*)(abase + pin0 * ROWB);
            a[1] = *(const unsigned*)(abase + pin1 * ROWB);
            a[2] = *(const unsigned*)(abase + pin0 * ROWB + 16);
            a[3] = *(const unsigned*)(abase + pin1 * ROWB + 16);
            #pragma unroll
            for (int nt = 0; nt < 4; nt++) {
                int co = wn * 32 + nt * 8 + g;
                const char* wbp = wcur + co * ROWB + chunk * 32 + t * 4;
                unsigned b0 = *(const unsigned*)wbp;
                unsigned b1 = *(const unsigned*)(wbp + 16);
                mma_u8s8(acch[nt], a, b0, b1);
            }
        }

        // ---- low conv, ci 0..127: fma pipe, broadcast LDS.128 weights ----
        const char* wlb = smem + WL_OFF + buf * WL_BUF + (wn * 4 + t) * 32;
        #pragma unroll
        for (int seg = 0; seg < 8; seg++) {
            uint4 a0 = *(const uint4*)(s_al + pin0 * ROWB + seg * 16);
            uint4 a1 = *(const uint4*)(s_al + pin1 * ROWB + seg * 16);
            const unsigned aw0[4] = {a0.x, a0.y, a0.z, a0.w};
            const unsigned aw1[4] = {a1.x, a1.y, a1.z, a1.w};
            #pragma unroll
            for (int q = 0; q < 4; q++) {
                const char* wp = wlb + (seg * 4 + q) * 256;
                uint4 wv0 = *(const uint4*)wp;
                uint4 wv1 = *(const uint4*)(wp + 16);
                accl[0][0] = dp4a_us(aw0[q], wv0.x, accl[0][0]);
                accl[0][1] = dp4a_us(aw0[q], wv0.y, accl[0][1]);
                accl[1][0] = dp4a_us(aw0[q], wv0.z, accl[1][0]);
                accl[1][1] = dp4a_us(aw0[q], wv0.w, accl[1][1]);
                accl[2][0] = dp4a_us(aw0[q], wv1.x, accl[2][0]);
                accl[2][1] = dp4a_us(aw0[q], wv1.y, accl[2][1]);
                accl[3][0] = dp4a_us(aw0[q], wv1.z, accl[3][0]);
                accl[3][1] = dp4a_us(aw0[q], wv1.w, accl[3][1]);
                accl[0][2] = dp4a_us(aw1[q], wv0.x, accl[0][2]);
                accl[0][3] = dp4a_us(aw1[q], wv0.y, accl[0][3]);
                accl[1][2] = dp4a_us(aw1[q], wv0.z, accl[1][2]);
                accl[1][3] = dp4a_us(aw1[q], wv0.w, accl[1][3]);
                accl[2][2] = dp4a_us(aw1[q], wv1.x, accl[2][2]);
                accl[2][3] = dp4a_us(aw1[q], wv1.y, accl[2][3]);
                accl[3][2] = dp4a_us(aw1[q], wv1.z, accl[3][2]);
                accl[3][3] = dp4a_us(aw1[q], wv1.w, accl[3][3]);
            }
        }

        // ---- high conv, ci 96..127: fma pipe -> accumulate into acch ----
        const char* whb = smem + WHD_OFF + buf * WHD_BUF + (wn * 4 + t) * 32;
        #pragma unroll
        for (int seg = 6; seg < 8; seg++) {
            uint4 a0 = *(const uint4*)(s_ah + pin0 * ROWB + seg * 16);
            uint4 a1 = *(const uint4*)(s_ah + pin1 * ROWB + seg * 16);
            const unsigned aw0[4] = {a0.x, a0.y, a0.z, a0.w};
            const unsigned aw1[4] = {a1.x, a1.y, a1.z, a1.w};
            #pragma unroll
            for (int q = 0; q < 4; q++) {
                const char* wp = whb + ((seg - 6) * 4 + q) * 256;
                uint4 wv0 = *(const uint4*)wp;
                uint4 wv1 = *(const uint4*)(wp + 16);
                acch[0][0] = dp4a_us(aw0[q], wv0.x, acch[0][0]);
                acch[0][1] = dp4a_us(aw0[q], wv0.y, acch[0][1]);
                acch[1][0] = dp4a_us(aw0[q], wv0.z, acch[1][0]);
                acch[1][1] = dp4a_us(aw0[q], wv0.w, acch[1][1]);
                acch[2][0] = dp4a_us(aw0[q], wv1.x, acch[2][0]);
                acch[2][1] = dp4a_us(aw0[q], wv1.y, acch[2][1]);
                acch[3][0] = dp4a_us(aw0[q], wv1.z, acch[3][0]);
                acch[3][1] = dp4a_us(aw0[q], wv1.w, acch[3][1]);
                acch[0][2] = dp4a_us(aw1[q], wv0.x, acch[0][2]);
                acch[0][3] = dp4a_us(aw1[q], wv0.y, acch[0][3]);
                acch[1][2] = dp4a_us(aw1[q], wv0.z, acch[1][2]);
                acch[1][3] = dp4a_us(aw1[q], wv0.w, acch[1][3]);
                acch[2][2] = dp4a_us(aw1[q], wv1.x, acch[2][2]);
                acch[2][3] = dp4a_us(aw1[q], wv1.y, acch[2][3]);
                acch[3][2] = dp4a_us(aw1[q], wv1.z, acch[3][2]);
                acch[3][3] = dp4a_us(aw1[q], wv1.w, acch[3][3]);
            }
        }
    }

    // epilogue: y = fsh*acc_h + fsl*acc_l -> NCHW fp32
    int p0 = wm * 16 + g;
    int oh0 = h0 + (p0 >> 3), ow = w0 + (p0 & 7);
    int oh1 = oh0 + 1;                               // pin1 row = next image row
    #pragma unroll
    for (int nt = 0; nt < 4; nt++) {
        int cg0 = co0 + wn * 32 + nt * 8 + t * 2;
        float sh0 = g_fsh[cg0],     sl0 = g_fsl[cg0];
        float sh1 = g_fsh[cg0 + 1], sl1 = g_fsl[cg0 + 1];
        out[((b * CC + cg0) * HH + oh0) * WW + ow] =
            sh0 * (float)acch[nt][0] + sl0 * (float)accl[nt][0];
        out[((b * CC + cg0 + 1) * HH + oh0) * WW + ow] =
            sh1 * (float)acch[nt][1] + sl1 * (float)accl[nt][1];
        out[((b * CC + cg0) * HH + oh1) * WW + ow] =
            sh0 * (float)acch[nt][2] + sl0 * (float)accl[nt][2];
        out[((b * CC + cg0 + 1) * HH + oh1) * WW + ow] =
            sh1 * (float)acch[nt][3] + sl1 * (float)accl[nt][3];
    }
}

// ---------------- launch ----------------
extern "C" void kernel_launch(void* const* d_in, const int* in_sizes, int n_in,
                              void* d_out, int out_size)
{
    const float* x      = (const float*)d_in[0];
    const float* w_high = (const float*)d_in[1];
    const float* w_low  = (const float*)d_in[2];
    const float* as_h   = (const float*)d_in[3];
    const float* as_l   = (const float*)d_in[4];
    float* out = (float*)d_out;

    cudaFuncSetAttribute(conv_hybrid_kernel,
                         cudaFuncAttributeMaxDynamicSharedMemorySize, CONV_SMEM);

    quant_weights_kernel<<<CC, 256>>>(w_high, as_h, 127.0f, 0);
    quant_weights_kernel<<<CC, 256>>>(w_low,  as_l,   7.0f, 1);
    mask_quant_kernel<<<dim3(WW / 8, HH / 8, BB), 256>>>(x, as_h, as_l);
    conv_hybrid_kernel<<<dim3(WW / 8, HH / 8, BB * 2), 256, CONV_SMEM>>>(out);
}

// round 10
// speedup vs baseline: 1.1240x; 1.0946x over previous
#include <cuda_runtime.h>
#include <cstdint>

#define BB 32
#define CC 128
#define HH 56
#define WW 56

// ---------------- scratch (module-static device memory; no allocs) ----------------
__device__ uint8_t g_ah[BB * HH * WW * CC];   // u8 high acts, NHWC (128 B/pixel)
__device__ uint8_t g_al[BB * HH * WW * CC];   // u8 low  acts, NHWC (128 B/pixel)
__device__ int8_t  g_wh[CC * 9 * CC];         // s8 high weights [co][k][ci] (mma path)
__device__ int8_t  g_wlT[9 * 2 * 32 * 64 * 4];// s8 low weights, dp4a broadcast layout
// T layout: [k][ch(co>>6)][ci4][wn][t][8 words]; word = nt*2+wb; byte = ci&3
__device__ float   g_fsh[CC];                 // fused scale high
__device__ float   g_fsl[CC];                 // fused scale low

__device__ __forceinline__ int dp4a_us(unsigned a, unsigned b, int c) {
    int r;
    asm("dp4a.u32.s32 %0, %1, %2, %3;" : "=r"(r) : "r"(a), "r"(b), "r"(c));
    return r;
}

// ---------------- K1: per-output-channel weight quantization ----------------
__global__ __launch_bounds__(256) void quant_weights_kernel(
    const float* __restrict__ w, const float* __restrict__ as_ptr,
    float nlev, int which)
{
    int co = blockIdx.x;
    int tid = threadIdx.x;
    const float* wc = w + co * (CC * 9);

    float mx = 0.f;
    for (int i = tid; i < CC * 9; i += 256) mx = fmaxf(mx, fabsf(wc[i]));
    __shared__ float red[256];
    red[tid] = mx;
    __syncthreads();
    for (int s = 128; s > 0; s >>= 1) {
        if (tid < s) red[tid] = fmaxf(red[tid], red[tid + s]);
        __syncthreads();
    }
    float s = red[0] / nlev;

    // decomposition for broadcast dp4a layout
    int ch = co >> 6, r = co & 63;
    int wn = r >> 5, r5 = r & 31;
    int nt = r5 >> 3, tt = (r5 >> 1) & 3, wb = r5 & 1;

    for (int i = tid; i < CC * 9; i += 256) {
        float q = rintf(wc[i] / s);
        q = fminf(fmaxf(q, -nlev), nlev);
        int ci = i / 9, k = i % 9;                 // OIHW: i = ci*9 + k
        if (which == 0) {
            g_wh[(co * 9 + k) * CC + ci] = (int8_t)q;
        } else {
            int ci4 = ci >> 2;
            int word = (((k * 2 + ch) * 32 + ci4) * 8 + wn * 4 + tt) * 8 + nt * 2 + wb;
            g_wlT[word * 4 + (ci & 3)] = (int8_t)q;
        }
    }
    if (tid == 0) {
        if (which) g_fsl[co] = s * as_ptr[0];
        else       g_fsh[co] = s * as_ptr[0];
    }
}

// ---------------- K2: predictor mask + activation fake-quant -> NHWC uint8 ----------------
__global__ __launch_bounds__(256) void mask_quant_kernel(
    const float* __restrict__ x,
    const float* __restrict__ ash_p, const float* __restrict__ asl_p)
{
    int bw = blockIdx.x, bh = blockIdx.y, b = blockIdx.z;
    int tid = threadIdx.x;
    int h0 = bh * 8, w0 = bw * 8;

    __shared__ float sx[64][CC + 1];
    __shared__ uint8_t smask[CC];

    for (int i = tid; i < 64 * CC; i += 256) {
        int c = i >> 6, p = i & 63;
        sx[p][c] = x[((b * CC + c) * HH + h0 + (p >> 3)) * WW + w0 + (p & 7)];
    }
    __syncthreads();

    int lane = tid & 31, wrp = tid >> 5;
    for (int j = 0; j < 16; j++) {
        int c = wrp * 16 + j;
        float v = sx[lane][c] + sx[lane + 32][c];
        #pragma unroll
        for (int o = 16; o > 0; o >>= 1) v += __shfl_xor_sync(0xffffffffu, v, o);
        if (lane == 0) smask[c] = (v * (1.0f / 64.0f) >= 0.05f) ? 1 : 0;
    }
    __syncthreads();

    float ash = ash_p[0], asl = asl_p[0];
    for (int i = tid; i < 64 * (CC / 4); i += 256) {
        int p = i >> 5, c4 = (i & 31);
        int hh = h0 + (p >> 3), ww = w0 + (p & 7);
        unsigned qh = 0u, ql = 0u;
        #pragma unroll
        for (int j = 0; j < 4; j++) {
            int c = c4 * 4 + j;
            float v = sx[p][c];
            bool m = smask[c] != 0;
            float fh = fminf(fmaxf(rintf(v / ash), 0.f), 255.f);
            float fl = fminf(fmaxf(rintf(v / asl), 0.f), 15.f);
            unsigned b8h = m ? (unsigned)fh : 0u;
            unsigned b8l = m ? 0u : (unsigned)fl;
            qh |= b8h << (8 * j);
            ql |= b8l << (8 * j);
        }
        int base = ((b * HH + hh) * WW + ww) * (CC / 4) + c4;
        ((unsigned*)g_ah)[base] = qh;
        ((unsigned*)g_al)[base] = ql;
    }
}

// ---------------- K3: hybrid conv3x3 — high via mma+ldmatrix, low via dp4a ----------------
// CTA: 256 thr, 8 warps (4M x 2N), warp = 16pix x 32co, tile 64 pix x 64 co.
// 3 CTAs/SM. mma fragments via LDSM.x4 (12 instr/tap vs 48 LDS.32);
// dp4a weights via broadcast LDS.128 layout (64 instr/tap vs 128 LDS.64).

#define ROWB 144
#define ACT_H_OFF 0
#define ACT_L_OFF 14400                         // 100*144
#define WH_OFF 28800
#define WH_BUF 9216                             // 64co * 144
#define WL_OFF (28800 + 2 * 9216)               // 47232
#define WL_BUF 8192                             // 32 ci4 * 256B
#define CONV_SMEM (WL_OFF + 2 * WL_BUF)         // 63616

__device__ __forceinline__ void mma_u8s8(int* c, const unsigned* a, unsigned b0, unsigned b1) {
    asm volatile(
        "mma.sync.aligned.m16n8k32.row.col.s32.u8.s8.s32 "
        "{%0,%1,%2,%3}, {%4,%5,%6,%7}, {%8,%9}, {%0,%1,%2,%3};"
        : "+r"(c[0]), "+r"(c[1]), "+r"(c[2]), "+r"(c[3])
        : "r"(a[0]), "r"(a[1]), "r"(a[2]), "r"(a[3]), "r"(b0), "r"(b1));
}

__device__ __forceinline__ void ldsm_x4(unsigned addr, unsigned* r) {
    asm volatile(
        "ldmatrix.sync.aligned.m8n8.x4.shared.b16 {%0,%1,%2,%3}, [%4];"
        : "=r"(r[0]), "=r"(r[1]), "=r"(r[2]), "=r"(r[3]) : "r"(addr));
}

__device__ __forceinline__ void stage_weights(char* smem, int buf, int k, int co0, int tid) {
    unsigned sb = (unsigned)__cvta_generic_to_shared(smem);
    int ch = co0 >> 6;
    #pragma unroll
    for (int j = 0; j < 4; j++) {
        int i = tid + j * 256;
        if (i < 512) {
            // high mma weights: 64 co x 8 c16
            int co = i >> 3, c16 = i & 7;
            const char* src = (const char*)g_wh + ((co0 + co) * 9 + k) * CC + c16 * 16;
            unsigned d = sb + WH_OFF + buf * WH_BUF + co * ROWB + c16 * 16;
            asm volatile("cp.async.cg.shared.global [%0], [%1], 16;" :: "r"(d), "l"(src));
        } else {
            // low dp4a weights: contiguous 8KB slice
            int r = i - 512;
            const char* src = (const char*)g_wlT + (k * 2 + ch) * 8192 + r * 16;
            unsigned d = sb + WL_OFF + buf * WL_BUF + r * 16;
            asm volatile("cp.async.cg.shared.global [%0], [%1], 16;" :: "r"(d), "l"(src));
        }
    }
}

__global__ __launch_bounds__(256, 3) void conv_hybrid_kernel(float* __restrict__ out)
{
    extern __shared__ __align__(16) char smem[];
    unsigned sb32 = (unsigned)__cvta_generic_to_shared(smem);

    int tid = threadIdx.x;
    int bz = blockIdx.z;
    int b = bz >> 1;
    int co0 = (bz & 1) * 64;
    int h0 = blockIdx.y * 8, w0 = blockIdx.x * 8;

    // act halo tiles (both convs): 1600 16B chunks; invalid -> zero store
    #pragma unroll
    for (int j = 0; j < 7; j++) {
        int i = tid + j * 256;
        if (i < 1600) {
            int cv = i / 800, r = i % 800;
            int p = r >> 3, c16 = r & 7;
            int pr = p / 10 - 1 + h0, pc = p % 10 - 1 + w0;
            char* dgen = smem + (cv ? ACT_L_OFF : ACT_H_OFF) + p * ROWB + c16 * 16;
            if (pr >= 0 && pr < HH && pc >= 0 && pc < WW) {
                const char* src = (const char*)(cv ? g_al : g_ah)
                                  + ((size_t)((b * HH + pr) * WW + pc)) * 128 + c16 * 16;
                unsigned d = (unsigned)__cvta_generic_to_shared(dgen);
                asm volatile("cp.async.cg.shared.global [%0], [%1], 16;" :: "r"(d), "l"(src));
            } else {
                *(uint4*)dgen = make_uint4(0u, 0u, 0u, 0u);
            }
        }
    }
    stage_weights(smem, 0, 0, co0, tid);
    asm volatile("cp.async.commit_group;" ::: "memory");

    int lane = tid & 31, warp = tid >> 5;
    int wm = warp >> 1;          // 0..3 : 16-pixel group
    int wn = warp & 1;           // 0..1 : 32-co group
    int g = lane >> 2, t = lane & 3;

    // ldmatrix lane roles
    int lg = lane & 7;           // row-within-matrix selector
    int rsel = (lane >> 3) & 1;  // 0 -> pin0 rows, 1 -> pin1 rows (A)
    int hi16 = (lane >> 4) & 1;  // 0 -> bytes 0..15, 1 -> bytes 16..31 (A)

    int acch[4][4], accl[4][4];  // [nt][e]; e: 0,1 = row pin0 co,co+1; 2,3 = row pin1
    #pragma unroll
    for (int nt = 0; nt < 4; nt++)
        #pragma unroll
        for (int q = 0; q < 4; q++) { acch[nt][q] = 0; accl[nt][q] = 0; }

    const char* s_al = smem + ACT_L_OFF;
    // B ldmatrix address: co row = wn*32 + lane (covers nt*8+r via lane = nt*8+r)
    unsigned bRow = sb32 + WH_OFF + (unsigned)(wn * 32 + lane) * ROWB;

    #pragma unroll 1
    for (int k9 = 0; k9 < 9; k9++) {
        asm volatile("cp.async.wait_group 0;" ::: "memory");
        __syncthreads();
        int buf = k9 & 1;
        if (k9 < 8) {
            stage_weights(smem, buf ^ 1, k9 + 1, co0, tid);
            asm volatile("cp.async.commit_group;" ::: "memory");
        }
        int kh = k9 / 3, kw = k9 - kh * 3;
        int pin0 = (2 * wm + kh) * 10 + g + kw;      // dp4a act row (this thread)
        int pin1 = pin0 + 10;

        // A ldmatrix base: row pin(lg) with rsel choosing pin0/pin1 rows, hi16 byte-half
        unsigned aAddr = sb32 + ACT_H_OFF
                       + (unsigned)(((2 * wm + kh) * 10 + lg + kw + 10 * rsel) * ROWB)
                       + (unsigned)(hi16 * 16);
        unsigned bAddr = bRow + (unsigned)(buf * WH_BUF);

        // ---- high conv: tensor pipe, fragments via LDSM ----
        #pragma unroll
        for (int chunk = 0; chunk < 4; chunk++) {
            unsigned a[4], bA[4], bB[4];
            ldsm_x4(aAddr + chunk * 32, a);
            ldsm_x4(bAddr + chunk * 32, bA);
            ldsm_x4(bAddr + chunk * 32 + 16, bB);
            #pragma unroll
            for (int nt = 0; nt < 4; nt++)
                mma_u8s8(acch[nt], a, bA[nt], bB[nt]);
        }

        // ---- low conv: fma pipe (dp4a), broadcast LDS.128 weights ----
        const char* wlb = smem + WL_OFF + buf * WL_BUF + (wn * 4 + t) * 32;
        #pragma unroll
        for (int seg = 0; seg < 8; seg++) {
            uint4 a0 = *(const uint4*)(s_al + pin0 * ROWB + seg * 16);
            uint4 a1 = *(const uint4*)(s_al + pin1 * ROWB + seg * 16);
            const unsigned aw0[4] = {a0.x, a0.y, a0.z, a0.w};
            const unsigned aw1[4] = {a1.x, a1.y, a1.z, a1.w};
            #pragma unroll
            for (int q = 0; q < 4; q++) {
                const char* wp = wlb + (seg * 4 + q) * 256;
                uint4 wv0 = *(const uint4*)wp;
                uint4 wv1 = *(const uint4*)(wp + 16);
                accl[0][0] = dp4a_us(aw0[q], wv0.x, accl[0][0]);
                accl[0][1] = dp4a_us(aw0[q], wv0.y, accl[0][1]);
                accl[1][0] = dp4a_us(aw0[q], wv0.z, accl[1][0]);
                accl[1][1] = dp4a_us(aw0[q], wv0.w, accl[1][1]);
                accl[2][0] = dp4a_us(aw0[q], wv1.x, accl[2][0]);
                accl[2][1] = dp4a_us(aw0[q], wv1.y, accl[2][1]);
                accl[3][0] = dp4a_us(aw0[q], wv1.z, accl[3][0]);
                accl[3][1] = dp4a_us(aw0[q], wv1.w, accl[3][1]);
                accl[0][2] = dp4a_us(aw1[q], wv0.x, accl[0][2]);
                accl[0][3] = dp4a_us(aw1[q], wv0.y, accl[0][3]);
                accl[1][2] = dp4a_us(aw1[q], wv0.z, accl[1][2]);
                accl[1][3] = dp4a_us(aw1[q], wv0.w, accl[1][3]);
                accl[2][2] = dp4a_us(aw1[q], wv1.x, accl[2][2]);
                accl[2][3] = dp4a_us(aw1[q], wv1.y, accl[2][3]);
                accl[3][2] = dp4a_us(aw1[q], wv1.z, accl[3][2]);
                accl[3][3] = dp4a_us(aw1[q], wv1.w, accl[3][3]);
            }
        }
    }

    // epilogue: y = fsh*acc_h + fsl*acc_l -> NCHW fp32
    int p0 = wm * 16 + g;
    int oh0 = h0 + (p0 >> 3), ow = w0 + (p0 & 7);
    int oh1 = oh0 + 1;                               // pin1 row = next image row
    #pragma unroll
    for (int nt = 0; nt < 4; nt++) {
        int cg0 = co0 + wn * 32 + nt * 8 + t * 2;
        float sh0 = g_fsh[cg0],     sl0 = g_fsl[cg0];
        float sh1 = g_fsh[cg0 + 1], sl1 = g_fsl[cg0 + 1];
        out[((b * CC + cg0) * HH + oh0) * WW + ow] =
            sh0 * (float)acch[nt][0] + sl0 * (float)accl[nt][0];
        out[((b * CC + cg0 + 1) * HH + oh0) * WW + ow] =
            sh1 * (float)acch[nt][1] + sl1 * (float)accl[nt][1];
        out[((b * CC + cg0) * HH + oh1) * WW + ow] =
            sh0 * (float)acch[nt][2] + sl0 * (float)accl[nt][2];
        out[((b * CC + cg0 + 1) * HH + oh1) * WW + ow] =
            sh1 * (float)acch[nt][3] + sl1 * (float)accl[nt][3];
    }
}

// ---------------- launch ----------------
extern "C" void kernel_launch(void* const* d_in, const int* in_sizes, int n_in,
                              void* d_out, int out_size)
{
    const float* x      = (const float*)d_in[0];
    const float* w_high = (const float*)d_in[1];
    const float* w_low  = (const float*)d_in[2];
    const float* as_h   = (const float*)d_in[3];
    const float* as_l   = (const float*)d_in[4];
    float* out = (float*)d_out;

    cudaFuncSetAttribute(conv_hybrid_kernel,
                         cudaFuncAttributeMaxDynamicSharedMemorySize, CONV_SMEM);

    quant_weights_kernel<<<CC, 256>>>(w_high, as_h, 127.0f, 0);
    quant_weights_kernel<<<CC, 256>>>(w_low,  as_l,   7.0f, 1);
    mask_quant_kernel<<<dim3(WW / 8, HH / 8, BB), 256>>>(x, as_h, as_l);
    conv_hybrid_kernel<<<dim3(WW / 8, HH / 8, BB * 2), 256, CONV_SMEM>>>(out);
}